// round 3
// baseline (speedup 1.0000x reference)
#include <cuda_runtime.h>

// Problem constants (B=2, N=8192 -> M=16384, fixed for this problem id)
#define MTOT   16384
#define BSHIFT 13
#define NCAND  256
#define CTAS   64
#define THR    256

// ---------------- scratch (device globals; zero-initialized at module load,
// and reset at the END of every launch so replays stay deterministic) -------
__device__ float4 g_gt[MTOT];        // gx, gy, gz, |g|^2
__device__ float4 g_pr[MTOT];        // -2px, -2py, -2pz, 0
__device__ float  g_fown[MTOT];      // f_ii via canonical fma chain
__device__ float2 g_p1[CTAS];        // per-CTA (sum w, sum w*err)
__device__ float2 g_pA[CTAS];        // per-CTA (bce label0 sum, count label0)
__device__ int    g_slist[MTOT];     // survivor rows
__device__ int    g_scnt;            // survivor count        (reset at end)
__device__ float  g_fb[4];           // s0, s1, c0, c1        (reset at end)
__device__ unsigned g_barc;          // barrier arrival count (self-resetting)
__device__ unsigned g_barg;          // barrier generation (monotonic)

__device__ __forceinline__ float fchain(float4 pr, float4 g) {
    // canonical: f = sg + (-2p).g  — identical chain everywhere
    return fmaf(pr.x, g.x, fmaf(pr.y, g.y, fmaf(pr.z, g.z, g.w)));
}

// gen-counter grid barrier; all 64 CTAs guaranteed co-resident (single wave)
__device__ __forceinline__ void grid_barrier() {
    __syncthreads();
    if (threadIdx.x == 0) {
        __threadfence();
        unsigned gen = atomicAdd(&g_barg, 0u);
        unsigned t = atomicAdd(&g_barc, 1u);
        if (t == CTAS - 1) {
            atomicExch(&g_barc, 0u);
            __threadfence();
            atomicAdd(&g_barg, 1u);
        } else {
            while (atomicAdd(&g_barg, 0u) == gen) __nanosleep(32);
        }
        __threadfence();
    }
    __syncthreads();
}

__device__ __forceinline__ float4 apply_pose(const float* __restrict__ pg, int i,
                                             const float* __restrict__ kb) {
    const float* P = pg + (i >> BSHIFT) * 12;
    float x = kb[3 * i], y = kb[3 * i + 1], z = kb[3 * i + 2];
    float gx = P[0] * x + P[1] * y + P[2]  * z + P[3];
    float gy = P[4] * x + P[5] * y + P[6]  * z + P[7];
    float gz = P[8] * x + P[9] * y + P[10] * z + P[11];
    return make_float4(gx, gy, gz, gx * gx + gy * gy + gz * gz);
}

__global__ __launch_bounds__(THR) void k_fused(const float* __restrict__ kb,
                                               const float* __restrict__ kw,
                                               const float* __restrict__ pg,
                                               const float* __restrict__ ow,
                                               const float* __restrict__ lg,
                                               float* __restrict__ out) {
    __shared__ __align__(16) float4 s_c[NCAND];
    __shared__ float sA[8], sB[8];
    int tid = threadIdx.x, lane = tid & 31, wid = tid >> 5;

    // ============ PHASE 1: prep + self-contained phase A ============
    int row = blockIdx.x * THR + tid;

    // candidate j for this CTA's shared set; recompute gt_j from inputs
    {
        unsigned h = blockIdx.x * 1664525u + 1013904223u;
        unsigned jc = (h + (unsigned)tid * 2654435761u) & (MTOT - 1);
        s_c[tid] = apply_pose(pg, (int)jc, kb);
    }

    // own row: gt, pr, fown, weighted L1 error
    float4 gt = apply_pose(pg, row, kb);
    float px = kw[3 * row], py = kw[3 * row + 1], pz = kw[3 * row + 2];
    float4 pr = make_float4(-2.0f * px, -2.0f * py, -2.0f * pz, 0.0f);
    float fo = fchain(pr, gt);
    g_gt[row] = gt;
    g_pr[row] = pr;
    g_fown[row] = fo;

    float w = ow[row];
    float err = fabsf(px - gt.x) + fabsf(py - gt.y) + fabsf(pz - gt.z);
    float sw = w, swe = w * err;
    #pragma unroll
    for (int off = 16; off; off >>= 1) {
        sw  += __shfl_down_sync(0xffffffffu, sw,  off);
        swe += __shfl_down_sync(0xffffffffu, swe, off);
    }
    if (lane == 0) { sA[wid] = sw; sB[wid] = swe; }
    __syncthreads();
    if (tid == 0) {
        float A = 0.f, Bv = 0.f;
        #pragma unroll
        for (int k = 0; k < 8; k++) { A += sA[k]; Bv += sB[k]; }
        g_p1[blockIdx.x] = make_float2(A, Bv);
    }

    // phase A: test 256 shared candidates against own diagonal
    const float INF = __int_as_float(0x7f800000);
    float m0 = INF, m1 = INF, m2 = INF, m3 = INF;
    #pragma unroll 4
    for (int k = 0; k < NCAND; k += 4) {
        m0 = fminf(m0, fchain(pr, s_c[k + 0]));
        m1 = fminf(m1, fchain(pr, s_c[k + 1]));
        m2 = fminf(m2, fchain(pr, s_c[k + 2]));
        m3 = fminf(m3, fchain(pr, s_c[k + 3]));
    }
    bool resolved = (fminf(fminf(m0, m1), fminf(m2, m3)) < fo);  // mask = 0

    float s0 = 0.f, c0 = 0.f;
    if (resolved) {
        float xv = lg[row];
        float lp = log1pf(expf(-fabsf(xv)));
        s0 = fmaxf(xv, 0.f) + lp;           // softplus(x), label 0
        c0 = 1.f;
    } else {
        g_slist[atomicAdd(&g_scnt, 1)] = row;
    }
    #pragma unroll
    for (int off = 16; off; off >>= 1) {
        s0 += __shfl_down_sync(0xffffffffu, s0, off);
        c0 += __shfl_down_sync(0xffffffffu, c0, off);
    }
    __syncthreads();            // sA/sB reuse
    if (lane == 0) { sA[wid] = s0; sB[wid] = c0; }
    __syncthreads();
    if (tid == 0) {
        float A = 0.f, C = 0.f;
        #pragma unroll
        for (int k = 0; k < 8; k++) { A += sA[k]; C += sB[k]; }
        g_pA[blockIdx.x] = make_float2(A, C);
    }

    grid_barrier();

    // ============ PHASE 2: exact full-row rescan for survivors ============
    {
        __shared__ float s_mn[THR / 32];
        int S = g_scnt;
        for (int s = blockIdx.x; s < S; s += CTAS) {
            int r = g_slist[s];
            float4 prr = g_pr[r];
            float a0 = INF, a1 = INF, a2 = INF, a3 = INF;
            #pragma unroll 2
            for (int j = tid; j < MTOT; j += 4 * THR) {
                a0 = fminf(a0, fchain(prr, g_gt[j]));
                a1 = fminf(a1, fchain(prr, g_gt[j + THR]));
                a2 = fminf(a2, fchain(prr, g_gt[j + 2 * THR]));
                a3 = fminf(a3, fchain(prr, g_gt[j + 3 * THR]));
            }
            float mn = fminf(fminf(a0, a1), fminf(a2, a3));
            #pragma unroll
            for (int off = 16; off; off >>= 1)
                mn = fminf(mn, __shfl_down_sync(0xffffffffu, mn, off));
            if (lane == 0) s_mn[wid] = mn;
            __syncthreads();
            if (tid == 0) {
                float m = s_mn[0];
                #pragma unroll
                for (int k = 1; k < THR / 32; k++) m = fminf(m, s_mn[k]);
                // scan includes j==r with identical chain -> m <= fown;
                // equality <=> nothing strictly closer <=> mask = 1
                bool mask = (g_fown[r] <= m);
                float xv = lg[r];
                float lp = log1pf(expf(-fabsf(xv)));
                if (mask) {
                    atomicAdd(&g_fb[1], fmaxf(-xv, 0.f) + lp);
                    atomicAdd(&g_fb[3], 1.f);
                } else {
                    atomicAdd(&g_fb[0], fmaxf(xv, 0.f) + lp);
                    atomicAdd(&g_fb[2], 1.f);
                }
            }
            __syncthreads();
        }
    }

    grid_barrier();

    // ============ PHASE 3: CTA 0 final reduce + scratch reset ============
    if (blockIdx.x == 0 && tid < 32) {
        float2 a0 = g_p1[tid], a1 = g_p1[tid + 32];
        float2 b0 = g_pA[tid], b1 = g_pA[tid + 32];
        float sw2  = a0.x + a1.x;
        float swe2 = a0.y + a1.y;
        float t0   = b0.x + b1.x;
        float n0   = b0.y + b1.y;
        #pragma unroll
        for (int off = 16; off; off >>= 1) {
            sw2  += __shfl_down_sync(0xffffffffu, sw2,  off);
            swe2 += __shfl_down_sync(0xffffffffu, swe2, off);
            t0   += __shfl_down_sync(0xffffffffu, t0,   off);
            n0   += __shfl_down_sync(0xffffffffu, n0,   off);
        }
        if (tid == 0) {
            t0 += g_fb[0];
            n0 += g_fb[2];
            float t1 = g_fb[1];
            float n1 = g_fb[3];
            float mean_err = swe2 / fmaxf(sw2, 1e-6f);
            float gr0 = (n0 > 0.f) ? (t0 / fmaxf(n0, 1.f)) : 0.f;
            float gr1 = (n1 > 0.f) ? (t1 / fmaxf(n1, 1.f)) : 0.f;
            out[0] = mean_err + 0.5f * gr0 + 0.5f * gr1;
            // reset cross-launch scratch for the next (replayed) launch
            g_scnt = 0;
            g_fb[0] = 0.f; g_fb[1] = 0.f; g_fb[2] = 0.f; g_fb[3] = 0.f;
        }
    }
}

// ---------------- launch: ONE kernel ----------------
extern "C" void kernel_launch(void* const* d_in, const int* in_sizes, int n_in,
                              void* d_out, int out_size) {
    const float* kb = (const float*)d_in[0];   // kp_before       (B,N,3)
    const float* kw = (const float*)d_in[1];   // kp_warped_pred  (B,N,3)
    const float* pg = (const float*)d_in[2];   // pose_gt         (B,3,4)
    const float* ow = (const float*)d_in[3];   // overlap_weights (B,N)
    const float* lg = (const float*)d_in[4];   // inlier_logits   (B,N)
    k_fused<<<CTAS, THR>>>(kb, kw, pg, ow, lg, (float*)d_out);
}

// round 4
// speedup vs baseline: 1.2297x; 1.2297x over previous
#include <cuda_runtime.h>

// Problem constants (B=2, N=8192 -> M=16384, fixed for this problem id)
#define MTOT   16384
#define BSHIFT 13
#define NCAND  256
#define CTAS1  128
#define THR1   128
#define CTAS2  128
#define THR2   256

// ---------------- scratch (device globals; zero at module load; the last
// CTA of K2 resets everything so graph replays are identical) --------------
__device__ float4 g_gt[MTOT];      // gx, gy, gz, |g|^2
__device__ float4 g_pr[MTOT];      // -2px, -2py, -2pz, 0
__device__ float  g_fown[MTOT];    // f_ii via canonical fma chain
__device__ int    g_slist[MTOT];   // survivor rows
__device__ int    g_scnt;          // survivor count
__device__ float  g_acc[4];        // sum_w, sum_w_err, bce0_sum(phaseA), cnt0(phaseA)
__device__ float  g_fb[4];         // fallback: s0, s1, c0, c1
__device__ unsigned g_done;        // K2 completion ticket

__device__ __forceinline__ float fchain(float4 pr, float4 g) {
    // canonical: f = sg + (-2p).g  — identical chain everywhere
    return fmaf(pr.x, g.x, fmaf(pr.y, g.y, fmaf(pr.z, g.z, g.w)));
}

__device__ __forceinline__ float4 apply_pose(const float* __restrict__ pg, int i,
                                             const float* __restrict__ kb) {
    const float* P = pg + (i >> BSHIFT) * 12;
    float x = kb[3 * i], y = kb[3 * i + 1], z = kb[3 * i + 2];
    float gx = P[0] * x + P[1] * y + P[2]  * z + P[3];
    float gy = P[4] * x + P[5] * y + P[6]  * z + P[7];
    float gz = P[8] * x + P[9] * y + P[10] * z + P[11];
    return make_float4(gx, gy, gz, gx * gx + gy * gy + gz * gz);
}

// ============ K1: prep + phase A (self-contained per CTA) ============
__global__ __launch_bounds__(THR1) void k1(const float* __restrict__ kb,
                                           const float* __restrict__ kw,
                                           const float* __restrict__ pg,
                                           const float* __restrict__ ow,
                                           const float* __restrict__ lg) {
    __shared__ __align__(16) float4 s_c[NCAND];
    __shared__ float sA[THR1 / 32], sB[THR1 / 32];
    int tid = threadIdx.x, lane = tid & 31, wid = tid >> 5;
    int row = blockIdx.x * THR1 + tid;

    // CTA-shared candidate set, recomputed from inputs (bit-identical chain)
    unsigned h = blockIdx.x * 1664525u + 1013904223u;
    #pragma unroll
    for (int k = tid; k < NCAND; k += THR1) {
        unsigned jc = (h + (unsigned)k * 2654435761u) & (MTOT - 1);
        s_c[k] = apply_pose(pg, (int)jc, kb);
    }

    // own row
    float4 gt = apply_pose(pg, row, kb);
    float px = kw[3 * row], py = kw[3 * row + 1], pz = kw[3 * row + 2];
    float4 pr = make_float4(-2.0f * px, -2.0f * py, -2.0f * pz, 0.0f);
    float fo = fchain(pr, gt);
    g_gt[row] = gt;
    g_pr[row] = pr;
    g_fown[row] = fo;

    // weighted L1 corr error partial
    float w = ow[row];
    float err = fabsf(px - gt.x) + fabsf(py - gt.y) + fabsf(pz - gt.z);
    float sw = w, swe = w * err;
    #pragma unroll
    for (int off = 16; off; off >>= 1) {
        sw  += __shfl_down_sync(0xffffffffu, sw,  off);
        swe += __shfl_down_sync(0xffffffffu, swe, off);
    }
    if (lane == 0) { sA[wid] = sw; sB[wid] = swe; }
    __syncthreads();
    if (tid == 0) {
        float A = 0.f, Bv = 0.f;
        #pragma unroll
        for (int k = 0; k < THR1 / 32; k++) { A += sA[k]; Bv += sB[k]; }
        atomicAdd(&g_acc[0], A);
        atomicAdd(&g_acc[1], Bv);
    }

    // phase A: 256 shared candidates vs own diagonal
    const float INF = __int_as_float(0x7f800000);
    float m0 = INF, m1 = INF, m2 = INF, m3 = INF;
    #pragma unroll 4
    for (int k = 0; k < NCAND; k += 4) {
        m0 = fminf(m0, fchain(pr, s_c[k + 0]));
        m1 = fminf(m1, fchain(pr, s_c[k + 1]));
        m2 = fminf(m2, fchain(pr, s_c[k + 2]));
        m3 = fminf(m3, fchain(pr, s_c[k + 3]));
    }
    bool resolved = (fminf(fminf(m0, m1), fminf(m2, m3)) < fo);  // mask = 0 proven

    float s0 = 0.f, c0 = 0.f;
    if (resolved) {
        float xv = lg[row];
        float lp = log1pf(expf(-fabsf(xv)));
        s0 = fmaxf(xv, 0.f) + lp;           // softplus(x), label 0
        c0 = 1.f;
    } else {
        g_slist[atomicAdd(&g_scnt, 1)] = row;
    }
    #pragma unroll
    for (int off = 16; off; off >>= 1) {
        s0 += __shfl_down_sync(0xffffffffu, s0, off);
        c0 += __shfl_down_sync(0xffffffffu, c0, off);
    }
    __syncthreads();
    if (lane == 0) { sA[wid] = s0; sB[wid] = c0; }
    __syncthreads();
    if (tid == 0) {
        float A = 0.f, C = 0.f;
        #pragma unroll
        for (int k = 0; k < THR1 / 32; k++) { A += sA[k]; C += sB[k]; }
        atomicAdd(&g_acc[2], A);
        atomicAdd(&g_acc[3], C);
    }
}

// ============ K2: survivor full-row rescan + last-CTA finalize ============
__global__ __launch_bounds__(THR2) void k2(const float* __restrict__ lg,
                                           float* __restrict__ out) {
    __shared__ float s_mn[THR2 / 32];
    int tid = threadIdx.x, lane = tid & 31, wid = tid >> 5;
    const float INF = __int_as_float(0x7f800000);
    int S = g_scnt;

    for (int s = blockIdx.x; s < S; s += CTAS2) {
        int r = g_slist[s];
        float4 prr = g_pr[r];
        float a0 = INF, a1 = INF, a2 = INF, a3 = INF;
        #pragma unroll 2
        for (int j = tid; j < MTOT; j += 4 * THR2) {
            a0 = fminf(a0, fchain(prr, g_gt[j]));
            a1 = fminf(a1, fchain(prr, g_gt[j + THR2]));
            a2 = fminf(a2, fchain(prr, g_gt[j + 2 * THR2]));
            a3 = fminf(a3, fchain(prr, g_gt[j + 3 * THR2]));
        }
        float mn = fminf(fminf(a0, a1), fminf(a2, a3));
        #pragma unroll
        for (int off = 16; off; off >>= 1)
            mn = fminf(mn, __shfl_down_sync(0xffffffffu, mn, off));
        if (lane == 0) s_mn[wid] = mn;
        __syncthreads();
        if (tid == 0) {
            float m = s_mn[0];
            #pragma unroll
            for (int k = 1; k < THR2 / 32; k++) m = fminf(m, s_mn[k]);
            // scan includes j==r with identical chain -> m <= fown;
            // equality <=> nothing strictly closer <=> mask = 1
            bool mask = (g_fown[r] <= m);
            float xv = lg[r];
            float lp = log1pf(expf(-fabsf(xv)));
            if (mask) {
                atomicAdd(&g_fb[1], fmaxf(-xv, 0.f) + lp);   // softplus(-x), label 1
                atomicAdd(&g_fb[3], 1.f);
            } else {
                atomicAdd(&g_fb[0], fmaxf(xv, 0.f) + lp);
                atomicAdd(&g_fb[2], 1.f);
            }
        }
        __syncthreads();
    }

    // last-CTA-done ticket: finalize + reset scratch for next graph replay
    if (tid == 0) {
        __threadfence();
        unsigned t = atomicAdd(&g_done, 1u);
        if (t == CTAS2 - 1) {
            float sw  = g_acc[0], swe = g_acc[1];
            float t0  = g_acc[2] + g_fb[0];
            float n0  = g_acc[3] + g_fb[2];
            float t1  = g_fb[1];
            float n1  = g_fb[3];
            float mean_err = swe / fmaxf(sw, 1e-6f);
            float gr0 = (n0 > 0.f) ? (t0 / fmaxf(n0, 1.f)) : 0.f;
            float gr1 = (n1 > 0.f) ? (t1 / fmaxf(n1, 1.f)) : 0.f;
            out[0] = mean_err + 0.5f * gr0 + 0.5f * gr1;
            // reset for the next launch/replay
            g_scnt = 0;
            g_done = 0u;
            #pragma unroll
            for (int k = 0; k < 4; k++) { g_acc[k] = 0.f; g_fb[k] = 0.f; }
            __threadfence();
        }
    }
}

// ---------------- launch: TWO kernels ----------------
extern "C" void kernel_launch(void* const* d_in, const int* in_sizes, int n_in,
                              void* d_out, int out_size) {
    const float* kb = (const float*)d_in[0];   // kp_before       (B,N,3)
    const float* kw = (const float*)d_in[1];   // kp_warped_pred  (B,N,3)
    const float* pg = (const float*)d_in[2];   // pose_gt         (B,3,4)
    const float* ow = (const float*)d_in[3];   // overlap_weights (B,N)
    const float* lg = (const float*)d_in[4];   // inlier_logits   (B,N)
    k1<<<CTAS1, THR1>>>(kb, kw, pg, ow, lg);
    k2<<<CTAS2, THR2>>>(lg, (float*)d_out);
}